// round 1
// baseline (speedup 1.0000x reference)
#include <cuda_runtime.h>

// CtaPostAttnMixer: 4-step fixed-boundary heat diffusion along seq dim.
// x: (B=4, L=8192, D=1024) fp32, y same.
//
// Interior rows (4 <= l <= L-5): closed-form 9-tap convolution along l with
// taps of (0.1 s^-1 + 0.8 + 0.1 s)^4. Boundary rows (0..3, L-4..L-1):
// explicit 4-step iteration on an 8-row window (outputs there depend only on
// the 8 edge rows, with the edge row itself held fixed).

constexpr int B  = 4;
constexpr int L  = 8192;
constexpr int D  = 1024;
constexpr int D4 = D / 4;          // float4 lanes per row
constexpr int L_CHUNK = 88;        // 8184 interior rows = 88 * 93 exactly
constexpr int NCHUNK  = (L - 8) / L_CHUNK;   // 93

// Taps of ((1-2a) + a*s + a*s^-1)^4 with a = 0.1 (symmetric)
__device__ __forceinline__ float tap0() { return 0.0001f; }
__device__ __forceinline__ float tap1() { return 0.0032f; }
__device__ __forceinline__ float tap2() { return 0.0388f; }
__device__ __forceinline__ float tap3() { return 0.2144f; }
__device__ __forceinline__ float tap4() { return 0.4870f; }

__global__ __launch_bounds__(256) void interior_kernel(
    const float* __restrict__ x, float* __restrict__ y)
{
    const int d4    = threadIdx.x;       // 0..255 (float4 column)
    const int chunk = blockIdx.x;        // 0..NCHUNK-1
    const int b     = blockIdx.y;        // 0..B-1

    const size_t base = (size_t)b * L * D;
    const float4* __restrict__ xb = reinterpret_cast<const float4*>(x + base) + d4;
    float4*       __restrict__ yb = reinterpret_cast<float4*>(y + base) + d4;

    const int l0   = 4 + chunk * L_CHUNK;
    const int lend = l0 + L_CHUNK;       // <= L-4 always (exact division)

    // Sliding window w[0..8] = rows l-4 .. l+4 (float4 each)
    float4 w[9];
#pragma unroll
    for (int k = 0; k < 9; ++k)
        w[k] = xb[(size_t)(l0 - 4 + k) * D4];

#pragma unroll 9
    for (int l = l0; l < lend; ++l) {
        // Prefetch next halo row early (guard only matters for the very last
        // chunk where l+5 would hit L).
        float4 nxt;
        const bool more = (l + 1 < lend);
        if (more) nxt = xb[(size_t)(l + 5) * D4];

        float4 o;
        o.x = tap4() * w[4].x
            + tap3() * (w[3].x + w[5].x)
            + tap2() * (w[2].x + w[6].x)
            + tap1() * (w[1].x + w[7].x)
            + tap0() * (w[0].x + w[8].x);
        o.y = tap4() * w[4].y
            + tap3() * (w[3].y + w[5].y)
            + tap2() * (w[2].y + w[6].y)
            + tap1() * (w[1].y + w[7].y)
            + tap0() * (w[0].y + w[8].y);
        o.z = tap4() * w[4].z
            + tap3() * (w[3].z + w[5].z)
            + tap2() * (w[2].z + w[6].z)
            + tap1() * (w[1].z + w[7].z)
            + tap0() * (w[0].z + w[8].z);
        o.w = tap4() * w[4].w
            + tap3() * (w[3].w + w[5].w)
            + tap2() * (w[2].w + w[6].w)
            + tap1() * (w[1].w + w[7].w)
            + tap0() * (w[0].w + w[8].w);

        yb[(size_t)l * D4] = o;

#pragma unroll
        for (int k = 0; k < 8; ++k) w[k] = w[k + 1];
        if (more) w[8] = nxt;
    }
}

__global__ __launch_bounds__(256) void boundary_kernel(
    const float* __restrict__ x, float* __restrict__ y)
{
    const int d4   = threadIdx.x;
    const int b    = blockIdx.x;
    const int side = blockIdx.y;         // 0 = left edge, 1 = right edge

    const size_t base = (size_t)b * L * D;
    const float4* __restrict__ xb = reinterpret_cast<const float4*>(x + base) + d4;
    float4*       __restrict__ yb = reinterpret_cast<float4*>(y + base) + d4;

    const int l0 = (side == 0) ? 0 : (L - 8);

    float4 w[8];
#pragma unroll
    for (int k = 0; k < 8; ++k)
        w[k] = xb[(size_t)(l0 + k) * D4];

    const float a = 0.1f;
    // 4 explicit steps. Update interior window indices 1..6 each step.
    // Left side: w[0] is the fixed global boundary; outputs are local 0..3
    // (their dependency cone never touches an updated w[7]).
    // Right side: w[7] is the fixed global boundary; outputs are local 4..7
    // (their dependency cone never touches an updated w[0]).
#pragma unroll
    for (int s = 0; s < 4; ++s) {
        float4 prev = w[0];
#pragma unroll
        for (int i = 1; i < 7; ++i) {
            float4 cur = w[i];
            float4 nb  = w[i + 1];
            float4 nv;
            nv.x = cur.x + a * (nb.x - 2.0f * cur.x + prev.x);
            nv.y = cur.y + a * (nb.y - 2.0f * cur.y + prev.y);
            nv.z = cur.z + a * (nb.z - 2.0f * cur.z + prev.z);
            nv.w = cur.w + a * (nb.w - 2.0f * cur.w + prev.w);
            w[i] = nv;
            prev = cur;
        }
    }

    const int wbeg = (side == 0) ? 0 : 4;
#pragma unroll
    for (int k = 0; k < 4; ++k)
        yb[(size_t)(l0 + wbeg + k) * D4] = w[wbeg + k];
}

extern "C" void kernel_launch(void* const* d_in, const int* in_sizes, int n_in,
                              void* d_out, int out_size)
{
    const float* x = (const float*)d_in[0];
    float*       y = (float*)d_out;

    interior_kernel<<<dim3(NCHUNK, B), 256>>>(x, y);
    boundary_kernel<<<dim3(B, 2), 256>>>(x, y);
}

// round 2
// speedup vs baseline: 1.3429x; 1.3429x over previous
#include <cuda_runtime.h>

// CtaPostAttnMixer: 4-step fixed-boundary heat diffusion along seq dim.
// x: (B=4, L=8192, D=1024) fp32.
//
// Interior rows (4 <= l <= L-5): closed-form 9-tap convolution (taps of
// (0.1 s^-1 + 0.8 + 0.1 s)^4). Boundary rows: explicit 4-step iteration on an
// 8-row edge window, fused into the first/last chunk blocks.
//
// R2: single fused launch; 4-deep load pipelining per warp (groups of 4 rows:
// issue 4 independent prefetch loads, then compute 4 outputs) to fix the
// MLP=1 latency bottleneck seen in R1 (~4.1 TB/s achieved).

constexpr int B  = 4;
constexpr int L  = 8192;
constexpr int D  = 1024;
constexpr int D4 = D / 4;            // float4 lanes per row
constexpr int L_CHUNK = 88;          // 8184 interior rows = 88 * 93 exactly
constexpr int NCHUNK  = (L - 8) / L_CHUNK;   // 93
constexpr int GROUP   = 4;           // rows per pipelined group (MLP depth)
constexpr int NGROUP  = L_CHUNK / GROUP;     // 22

// Taps of ((1-2a) + a*s + a*s^-1)^4 with a = 0.1 (symmetric, sums to 1)
constexpr float T0 = 0.0001f;
constexpr float T1 = 0.0032f;
constexpr float T2 = 0.0388f;
constexpr float T3 = 0.2144f;
constexpr float T4 = 0.4870f;

__device__ __forceinline__ float4 conv9(const float4* w)
{
    float4 o;
    o.x = T4 * w[4].x + T3 * (w[3].x + w[5].x) + T2 * (w[2].x + w[6].x)
        + T1 * (w[1].x + w[7].x) + T0 * (w[0].x + w[8].x);
    o.y = T4 * w[4].y + T3 * (w[3].y + w[5].y) + T2 * (w[2].y + w[6].y)
        + T1 * (w[1].y + w[7].y) + T0 * (w[0].y + w[8].y);
    o.z = T4 * w[4].z + T3 * (w[3].z + w[5].z) + T2 * (w[2].z + w[6].z)
        + T1 * (w[1].z + w[7].z) + T0 * (w[0].z + w[8].z);
    o.w = T4 * w[4].w + T3 * (w[3].w + w[5].w) + T2 * (w[2].w + w[6].w)
        + T1 * (w[1].w + w[7].w) + T0 * (w[0].w + w[8].w);
    return o;
}

__global__ __launch_bounds__(256) void mixer_kernel(
    const float* __restrict__ x, float* __restrict__ y)
{
    const int d4    = threadIdx.x;       // 0..255 (float4 column)
    const int chunk = blockIdx.x;        // 0..NCHUNK-1
    const int b     = blockIdx.y;        // 0..B-1

    const size_t base = (size_t)b * L * D;
    const float4* __restrict__ xb = reinterpret_cast<const float4*>(x + base) + d4;
    float4*       __restrict__ yb = reinterpret_cast<float4*>(y + base) + d4;

    const int l0 = 4 + chunk * L_CHUNK;

    // ---- Interior: 9-row sliding window, 4-deep prefetch pipeline ----
    float4 w[9];
#pragma unroll
    for (int k = 0; k < 9; ++k)
        w[k] = xb[(size_t)(l0 - 4 + k) * D4];

    int l = l0;
#pragma unroll 1
    for (int g = 0; g < NGROUP; ++g) {
        // Issue GROUP independent loads back-to-back (rows l+5 .. l+8),
        // clamped at L-1 (only the final chunk's final group ever clamps,
        // and the clamped value is never consumed by an output).
        float4 p[GROUP];
#pragma unroll
        for (int j = 0; j < GROUP; ++j) {
            int idx = l + 5 + j;
            if (idx > L - 1) idx = L - 1;
            p[j] = xb[(size_t)idx * D4];
        }

#pragma unroll
        for (int j = 0; j < GROUP; ++j) {
            yb[(size_t)(l + j) * D4] = conv9(w);
#pragma unroll
            for (int k = 0; k < 8; ++k) w[k] = w[k + 1];
            w[8] = p[j];
        }
        l += GROUP;
    }

    // ---- Fused boundary: 4-step explicit iteration on 8-row edge window ----
    const bool left  = (chunk == 0);
    const bool right = (chunk == NCHUNK - 1);
    if (left || right) {
        const int e0 = left ? 0 : (L - 8);

        float4 e[8];
#pragma unroll
        for (int k = 0; k < 8; ++k)
            e[k] = xb[(size_t)(e0 + k) * D4];     // L2-hot

        const float a = 0.1f;
#pragma unroll
        for (int s = 0; s < 4; ++s) {
            float4 prev = e[0];
#pragma unroll
            for (int i = 1; i < 7; ++i) {
                float4 cur = e[i];
                float4 nb  = e[i + 1];
                float4 nv;
                nv.x = cur.x + a * (nb.x - 2.0f * cur.x + prev.x);
                nv.y = cur.y + a * (nb.y - 2.0f * cur.y + prev.y);
                nv.z = cur.z + a * (nb.z - 2.0f * cur.z + prev.z);
                nv.w = cur.w + a * (nb.w - 2.0f * cur.w + prev.w);
                e[i] = nv;
                prev = cur;
            }
        }

        // Left edge outputs rows 0..3 (e[0] is the fixed boundary, emitted
        // as-is); right edge outputs rows L-4..L-1 (e[7] fixed).
        const int wbeg = left ? 0 : 4;
#pragma unroll
        for (int k = 0; k < 4; ++k)
            yb[(size_t)(e0 + wbeg + k) * D4] = e[wbeg + k];
    }
}

extern "C" void kernel_launch(void* const* d_in, const int* in_sizes, int n_in,
                              void* d_out, int out_size)
{
    const float* x = (const float*)d_in[0];
    float*       y = (float*)d_out;

    mixer_kernel<<<dim3(NCHUNK, B), 256>>>(x, y);
}

// round 4
// speedup vs baseline: 1.4630x; 1.0895x over previous
#include <cuda_runtime.h>

// CtaPostAttnMixer: 4-step fixed-boundary heat diffusion along seq dim.
// x: (B=4, L=8192, D=1024) fp32.
//
// Interior rows (4 <= l <= L-5): closed-form 9-tap convolution (taps of
// (0.1 s^-1 + 0.8 + 0.1 s)^4). Boundary rows: explicit 4-step iteration on an
// 8-row edge window, fused into dedicated edge blocks.
//
// R3: grid = 148 x 4 = 592 blocks (one full wave at 4 blocks/SM, 32 warps/SM)
// to fix the 2.5-blocks/SM concurrency shortfall seen in R2 (DRAM 60.7%).
// Chunks of 56 rows (last real chunk short); chunk 147 has no interior rows
// and handles the right edge.

constexpr int B  = 4;
constexpr int L  = 8192;
constexpr int D  = 1024;
constexpr int D4 = D / 4;            // float4 lanes per row
constexpr int L_CHUNK = 56;          // rows per block (interior)
constexpr int NCHUNK  = 148;         // 148 chunks x 4 batches = 592 blocks
constexpr int GROUP   = 4;           // rows per pipelined group (MLP depth)

// Taps of ((1-2a) + a*s + a*s^-1)^4 with a = 0.1 (symmetric, sums to 1)
constexpr float T0 = 0.0001f;
constexpr float T1 = 0.0032f;
constexpr float T2 = 0.0388f;
constexpr float T3 = 0.2144f;
constexpr float T4 = 0.4870f;

__device__ __forceinline__ float4 conv9(const float4* w)
{
    float4 o;
    o.x = T4 * w[4].x + T3 * (w[3].x + w[5].x) + T2 * (w[2].x + w[6].x)
        + T1 * (w[1].x + w[7].x) + T0 * (w[0].x + w[8].x);
    o.y = T4 * w[4].y + T3 * (w[3].y + w[5].y) + T2 * (w[2].y + w[6].y)
        + T1 * (w[1].y + w[7].y) + T0 * (w[0].y + w[8].y);
    o.z = T4 * w[4].z + T3 * (w[3].z + w[5].z) + T2 * (w[2].z + w[6].z)
        + T1 * (w[1].z + w[7].z) + T0 * (w[0].z + w[8].z);
    o.w = T4 * w[4].w + T3 * (w[3].w + w[5].w) + T2 * (w[2].w + w[6].w)
        + T1 * (w[1].w + w[7].w) + T0 * (w[0].w + w[8].w);
    return o;
}

__global__ __launch_bounds__(256, 4) void mixer_kernel(
    const float* __restrict__ x, float* __restrict__ y)
{
    const int d4    = threadIdx.x;       // 0..255 (float4 column)
    const int chunk = blockIdx.x;        // 0..NCHUNK-1
    const int b     = blockIdx.y;        // 0..B-1

    const size_t base = (size_t)b * L * D;
    const float4* __restrict__ xb = reinterpret_cast<const float4*>(x + base) + d4;
    float4*       __restrict__ yb = reinterpret_cast<float4*>(y + base) + d4;

    const int l0   = 4 + chunk * L_CHUNK;
    int lend = l0 + L_CHUNK;
    if (lend > L - 4) lend = L - 4;

    // ---- Interior: 9-row sliding window, 4-deep prefetch per group ----
    if (l0 < lend) {
        float4 w[9];
#pragma unroll
        for (int k = 0; k < 9; ++k)
            w[k] = xb[(size_t)(l0 - 4 + k) * D4];

        int l = l0;
#pragma unroll 1
        for (; l < lend; l += GROUP) {
            // Issue GROUP independent loads back-to-back (rows l+5 .. l+8),
            // clamped at L-1 (clamped values never reach an emitted output).
            float4 p[GROUP];
#pragma unroll
            for (int j = 0; j < GROUP; ++j) {
                int idx = l + 5 + j;
                if (idx > L - 1) idx = L - 1;
                p[j] = xb[(size_t)idx * D4];
            }

#pragma unroll
            for (int j = 0; j < GROUP; ++j) {
                yb[(size_t)(l + j) * D4] = conv9(w);
#pragma unroll
                for (int k = 0; k < 8; ++k) w[k] = w[k + 1];
                w[8] = p[j];
            }
        }
    }

    // ---- Fused boundary: 4-step explicit iteration on 8-row edge window ----
    const bool left  = (chunk == 0);
    const bool right = (chunk == NCHUNK - 1);   // chunk 147: no interior rows
    if (left || right) {
        const int e0 = left ? 0 : (L - 8);

        float4 e[8];
#pragma unroll
        for (int k = 0; k < 8; ++k)
            e[k] = xb[(size_t)(e0 + k) * D4];

        const float a = 0.1f;
#pragma unroll
        for (int s = 0; s < 4; ++s) {
            float4 prev = e[0];
#pragma unroll
            for (int i = 1; i < 7; ++i) {
                float4 cur = e[i];
                float4 nb  = e[i + 1];
                float4 nv;
                nv.x = cur.x + a * (nb.x - 2.0f * cur.x + prev.x);
                nv.y = cur.y + a * (nb.y - 2.0f * cur.y + prev.y);
                nv.z = cur.z + a * (nb.z - 2.0f * cur.z + prev.z);
                nv.w = cur.w + a * (nb.w - 2.0f * cur.w + prev.w);
                e[i] = nv;
                prev = cur;
            }
        }

        // Left edge: rows 0..3 (e[0] is the fixed boundary, emitted as-is);
        // right edge: rows L-4..L-1 (e[7] fixed).
        const int wbeg = left ? 0 : 4;
#pragma unroll
        for (int k = 0; k < 4; ++k)
            yb[(size_t)(e0 + wbeg + k) * D4] = e[wbeg + k];
    }
}

extern "C" void kernel_launch(void* const* d_in, const int* in_sizes, int n_in,
                              void* d_out, int out_size)
{
    const float* x = (const float*)d_in[0];
    float*       y = (float*)d_out;

    mixer_kernel<<<dim3(NCHUNK, B), 256>>>(x, y);
}